// round 1
// baseline (speedup 1.0000x reference)
#include <cuda_runtime.h>
#include <cstdint>

// Problem constants (fixed by the reference)
#define Bsz      4096
#define Tmax     512
#define Vv       57
#define Ee       20
#define Hh       128
#define Oo       18

// Partitioning
#define RR       8            // batch rows per CTA
#define NTHREADS 128          // one thread per hidden column j
#define NCTAS    (Bsz / RR)   // 512

// ---------------------------------------------------------------------------
// packed fp32x2 helpers (B300: FFMA2 doubles fp32 FMA throughput; ptxas never
// auto-generates it from C++ — must come from PTX fma.rn.f32x2)
// ---------------------------------------------------------------------------
__device__ __forceinline__ unsigned long long fma2(unsigned long long a,
                                                   unsigned long long b,
                                                   unsigned long long c) {
    unsigned long long d;
    asm("fma.rn.f32x2 %0, %1, %2, %3;" : "=l"(d) : "l"(a), "l"(b), "l"(c));
    return d;
}
__device__ __forceinline__ float2 unpack2(unsigned long long v) {
    float2 r;
    asm("mov.b64 {%0, %1}, %2;" : "=f"(r.x), "=f"(r.y) : "l"(v));
    return r;
}

// Accurate-enough tanh that is safe under --use_fast_math (no MUFU.TANH,
// no expf overflow: exponent argument is always <= 0).
__device__ __forceinline__ float tanh_acc(float x) {
    float ax = fabsf(x);
    float e  = exp2f(-2.8853900817779268f * ax);   // exp(-2*ax)
    float t  = (1.0f - e) / (1.0f + e);
    return copysignf(t, x);
}

// ---------------------------------------------------------------------------
// One kernel does everything:
//   1) embW[v][j] = sum_e emb[v][e]*W_ih[j][e] + b_ih[j] + b_hh[j]   (smem table)
//   2) recurrence: h[r] = tanh(embW[tok] + h[r] @ W_hh^T), masked by length,
//      W_hh row j held in registers (64 packed f32x2), h broadcast from smem
//   3) head: logits = relu(hT) @ W_out^T + b_out, log_softmax, write out
// ---------------------------------------------------------------------------
__global__ void __launch_bounds__(NTHREADS, 3) rnn_kernel(
    const int*   __restrict__ x,      // [B, T] token ids
    const int*   __restrict__ xlen,   // [B] lengths, sorted descending
    const float* __restrict__ emb,    // [V, E]
    const float* __restrict__ W_ih,   // [H, E]
    const float* __restrict__ W_hh,   // [H, H]
    const float* __restrict__ b_ih,   // [H]
    const float* __restrict__ b_hh,   // [H]
    const float* __restrict__ W_out,  // [O, H]
    const float* __restrict__ b_out,  // [O]
    float*       __restrict__ out)    // [B, O]
{
    __shared__ float embW[Vv * Hh];                         // 29184 B
    __shared__ __align__(16) float hbuf[2][RR][Hh];         //  8192 B (double buffer)
    __shared__ float Wout_s[Oo * 129];                      //  9288 B (pad 129: no bank conflicts)
    __shared__ float logits_s[RR * Oo];
    __shared__ int   lens_s[RR];

    const int j    = threadIdx.x;          // hidden column this thread owns
    const int row0 = blockIdx.x * RR;      // first batch row of this CTA

    // ---- stage emb into hbuf scratch; load W_out (padded); load lengths ----
    float* stage = &hbuf[0][0][0];         // V*E = 1140 floats < 2048 available
    for (int i = j; i < Vv * Ee; i += NTHREADS) stage[i] = emb[i];
    for (int i = j; i < Oo * Hh; i += NTHREADS)
        Wout_s[(i / Hh) * 129 + (i % Hh)] = W_out[i];
    if (j < RR) lens_s[j] = xlen[row0 + j];
    __syncthreads();

    // ---- embW column j: fuse input projection + both biases ----
    {
        float wih[Ee];
        #pragma unroll
        for (int e = 0; e < Ee; e++) wih[e] = W_ih[j * Ee + e];
        const float bias = b_ih[j] + b_hh[j];
        for (int v = 0; v < Vv; v++) {
            float s = bias;
            #pragma unroll
            for (int e = 0; e < Ee; e++) s = fmaf(stage[v * Ee + e], wih[e], s);
            embW[v * Hh + j] = s;
        }
    }
    __syncthreads();   // all reads of stage done before hbuf is reused

    // ---- init h = 0; cache lengths; compute CTA maxlen ----
    #pragma unroll
    for (int r = 0; r < RR; r++) hbuf[0][r][j] = 0.0f;

    int lr[RR];
    int maxlen = 1;
    #pragma unroll
    for (int r = 0; r < RR; r++) { lr[r] = lens_s[r]; maxlen = max(maxlen, lr[r]); }

    // ---- W_hh row j into 64 packed f32x2 registers ----
    unsigned long long w[Hh / 2];
    {
        const unsigned long long* wrow =
            reinterpret_cast<const unsigned long long*>(W_hh + j * Hh);
        #pragma unroll
        for (int i = 0; i < Hh / 2; i++) w[i] = wrow[i];
    }
    __syncthreads();

    // =========================== recurrence ===========================
    for (int t = 0; t < maxlen; t++) {
        const int cur = t & 1, nxt = cur ^ 1;
        #pragma unroll 1
        for (int r = 0; r < RR; r++) {
            if (t < lr[r]) {                                  // uniform branch
                const int tok = __ldg(&x[(row0 + r) * Tmax + t]);
                const ulonglong2* hp =
                    reinterpret_cast<const ulonglong2*>(&hbuf[cur][r][0]);
                unsigned long long a0 = 0ull, a1 = 0ull, a2 = 0ull, a3 = 0ull;
                #pragma unroll
                for (int kk = 0; kk < 32; kk += 2) {
                    ulonglong2 h2a = hp[kk];                  // LDS.128 broadcast
                    a0 = fma2(h2a.x, w[2 * kk + 0], a0);
                    a1 = fma2(h2a.y, w[2 * kk + 1], a1);
                    ulonglong2 h2b = hp[kk + 1];
                    a2 = fma2(h2b.x, w[2 * kk + 2], a2);
                    a3 = fma2(h2b.y, w[2 * kk + 3], a3);
                }
                float2 f0 = unpack2(a0), f1 = unpack2(a1);
                float2 f2 = unpack2(a2), f3 = unpack2(a3);
                float s = ((f0.x + f1.x) + (f0.y + f1.y))
                        + ((f2.x + f3.x) + (f2.y + f3.y));
                s += embW[tok * Hh + j];
                hbuf[nxt][r][j] = tanh_acc(s);
            } else {
                hbuf[nxt][r][j] = hbuf[cur][r][j];            // dead row: carry
            }
        }
        __syncthreads();
    }
    const int fin = maxlen & 1;   // buffer holding final h for all rows

    // =========================== output head ===========================
    for (int idx = j; idx < RR * Oo; idx += NTHREADS) {
        const int r = idx / Oo, o = idx % Oo;
        const float* hr = &hbuf[fin][r][0];
        float s = b_out[o];
        #pragma unroll 4
        for (int k = 0; k < Hh; k++)
            s = fmaf(fmaxf(hr[k], 0.0f), Wout_s[o * 129 + k], s);
        logits_s[idx] = s;
    }
    __syncthreads();

    if (j < RR) {
        float m = -1e30f;
        #pragma unroll
        for (int o = 0; o < Oo; o++) m = fmaxf(m, logits_s[j * Oo + o]);
        float se = 0.0f;
        #pragma unroll
        for (int o = 0; o < Oo; o++) se += expf(logits_s[j * Oo + o] - m);
        const float lse = m + logf(se);
        #pragma unroll
        for (int o = 0; o < Oo; o++)
            out[(row0 + j) * Oo + o] = logits_s[j * Oo + o] - lse;
    }
}

// ---------------------------------------------------------------------------
// Harness entry. Inputs in setup_inputs order:
//   0:x(int32) 1:x_lengths(int32) 2:emb 3:W_ih 4:W_hh 5:b_ih 6:b_hh 7:W_out 8:b_out
// Output: float32 [B, O]
// ---------------------------------------------------------------------------
extern "C" void kernel_launch(void* const* d_in, const int* in_sizes, int n_in,
                              void* d_out, int out_size) {
    const int*   x     = (const int*)  d_in[0];
    const int*   xlen  = (const int*)  d_in[1];
    const float* emb   = (const float*)d_in[2];
    const float* W_ih  = (const float*)d_in[3];
    const float* W_hh  = (const float*)d_in[4];
    const float* b_ih  = (const float*)d_in[5];
    const float* b_hh  = (const float*)d_in[6];
    const float* W_out = (const float*)d_in[7];
    const float* b_out = (const float*)d_in[8];

    rnn_kernel<<<NCTAS, NTHREADS>>>(x, xlen, emb, W_ih, W_hh,
                                    b_ih, b_hh, W_out, b_out,
                                    (float*)d_out);
}

// round 2
// speedup vs baseline: 1.4111x; 1.4111x over previous
#include <cuda_runtime.h>
#include <cstdint>

// Problem constants (fixed by the reference)
#define Bsz      4096
#define Tmax     512
#define Vv       57
#define Ee       20
#define Hh       128
#define Oo       18

// Partitioning
#define RR       8            // batch rows per CTA
#define NT       128          // 64 column-pairs x 2 k-halves
#define NCTAS    (Bsz / RR)   // 512

// h row layout in smem: words [0..63] = k 0..63, gap [64..67], [68..131] = k 64..127.
// The 4-word gap makes the two half-warp LDS.128 addresses hit disjoint banks.
#define HROW     132

// ---------------------------------------------------------------------------
// packed fp32x2 FMA (B300 FFMA2: 2x fp32 FMA throughput; PTX-only)
// ---------------------------------------------------------------------------
__device__ __forceinline__ unsigned long long fma2(unsigned long long a,
                                                   unsigned long long b,
                                                   unsigned long long c) {
    unsigned long long d;
    asm("fma.rn.f32x2 %0, %1, %2, %3;" : "=l"(d) : "l"(a), "l"(b), "l"(c));
    return d;
}
__device__ __forceinline__ float2 unpack2(unsigned long long v) {
    float2 r;
    asm("mov.b64 {%0, %1}, %2;" : "=f"(r.x), "=f"(r.y) : "l"(v));
    return r;
}
__device__ __forceinline__ float ex2a(float x) {
    float y; asm("ex2.approx.f32 %0, %1;" : "=f"(y) : "f"(x)); return y;
}
__device__ __forceinline__ float rcpa(float x) {
    float y; asm("rcp.approx.f32 %0, %1;" : "=f"(y) : "f"(x)); return y;
}
// tanh: 2 MUFU + 3 FMA-class ops, ~1e-6 rel err, no overflow (exponent <= 0)
__device__ __forceinline__ float tanh_fast(float x) {
    float ax = fabsf(x);
    float e  = ex2a(ax * -2.885390081777927f);     // exp(-2*ax)
    float t  = (1.0f - e) * rcpa(1.0f + e);
    return copysignf(t, x);
}

// ---------------------------------------------------------------------------
__global__ void __launch_bounds__(NT, 3) rnn_kernel(
    const int*   __restrict__ x,      // [B, T]
    const int*   __restrict__ xlen,   // [B] sorted descending
    const float* __restrict__ emb,    // [V, E]
    const float* __restrict__ W_ih,   // [H, E]
    const float* __restrict__ W_hh,   // [H, H]
    const float* __restrict__ b_ih,   // [H]
    const float* __restrict__ b_hh,   // [H]
    const float* __restrict__ W_out,  // [O, H]
    const float* __restrict__ b_out,  // [O]
    float*       __restrict__ out)    // [B, O]
{
    __shared__ __align__(16) float embW[Vv * Hh];        // 29184 B
    __shared__ __align__(16) float hbuf[2][RR][HROW];    //  8448 B
    __shared__ float Wout_s[Oo * 129];                   //  9288 B
    __shared__ float logits_s[RR * Oo];
    __shared__ int   lens_s[RR];
    __shared__ int   toks[2][RR];

    const int tid  = threadIdx.x;
    const int w    = tid >> 5, l = tid & 31;
    const int jp   = (w << 4) | (l & 15);   // column pair index 0..63
    const int half = l >> 4;                // k half: 0 -> k[0,64), 1 -> k[64,128)
    const int j0   = jp * 2;                // first of the two owned columns
    const int row0 = blockIdx.x * RR;

    // ---- stage emb into hbuf scratch (2112 floats available >= 1140) ----
    float* stage = &hbuf[0][0][0];
    for (int i = tid; i < Vv * Ee; i += NT) stage[i] = emb[i];
    for (int i = tid; i < Oo * Hh; i += NT)
        Wout_s[(i / Hh) * 129 + (i % Hh)] = W_out[i];
    if (tid < RR) {
        lens_s[tid] = xlen[row0 + tid];
        toks[0][tid] = x[(row0 + tid) * Tmax];           // tokens for t=0
    }
    __syncthreads();

    // ---- embW column tid: fused input projection + both biases ----
    {
        float wih[Ee];
        #pragma unroll
        for (int e = 0; e < Ee; e++) wih[e] = W_ih[tid * Ee + e];
        const float bias = b_ih[tid] + b_hh[tid];
        for (int v = 0; v < Vv; v++) {
            float s = bias;
            #pragma unroll
            for (int e = 0; e < Ee; e++) s = fmaf(stage[v * Ee + e], wih[e], s);
            embW[v * Hh + tid] = s;
        }
    }
    __syncthreads();   // stage reads complete before hbuf reuse

    // ---- zero h (buffer 0), cache lengths ----
    for (int i = tid; i < RR * HROW; i += NT) (&hbuf[0][0][0])[i] = 0.0f;

    int lr[RR]; int maxlen = 1;
    #pragma unroll
    for (int r = 0; r < RR; r++) { lr[r] = lens_s[r]; maxlen = max(maxlen, lr[r]); }

    // ---- W_hh: two columns (rows of W_hh), this thread's k-half: 128 regs ----
    unsigned long long w0[32], w1[32];
    {
        const ulonglong2* p0 = reinterpret_cast<const ulonglong2*>(W_hh + j0 * Hh + half * 64);
        const ulonglong2* p1 = reinterpret_cast<const ulonglong2*>(W_hh + (j0 + 1) * Hh + half * 64);
        #pragma unroll
        for (int i = 0; i < 16; i++) {
            ulonglong2 a = p0[i]; w0[2*i] = a.x; w0[2*i+1] = a.y;
            ulonglong2 b = p1[i]; w1[2*i] = b.x; w1[2*i+1] = b.y;
        }
    }
    __syncthreads();

    // smem word where this thread's column pair lives (skip the 4-word gap)
    const int hword = j0 + ((jp >= 32) ? 4 : 0);
    int nact = RR;   // active rows form a shrinking prefix (lengths sorted desc)

    // =========================== recurrence ===========================
    for (int t = 0; t < maxlen; t++) {
        const int cur = t & 1, nxt = cur ^ 1;
        // prefetch next step's tokens (latency hidden under this step's math)
        if (tid < RR) {
            const int tt = min(t + 1, Tmax - 1);
            toks[nxt][tid] = x[(row0 + tid) * Tmax + tt];
        }
        while (nact > 0 && lr[nact - 1] <= t) nact--;

        #pragma unroll 1
        for (int r = 0; r < nact; r++) {
            const int   tok = toks[cur][r];
            const float2 eb = *reinterpret_cast<const float2*>(&embW[tok * Hh + j0]);
            const ulonglong2* hp =
                reinterpret_cast<const ulonglong2*>(&hbuf[cur][r][half * 68]);
            unsigned long long a00 = 0ull, a01 = 0ull, a10 = 0ull, a11 = 0ull;
            #pragma unroll
            for (int kk = 0; kk < 16; kk++) {
                ulonglong2 h2 = hp[kk];            // one LDS.128 feeds 4 FFMA2
                a00 = fma2(h2.x, w0[2*kk],     a00);
                a01 = fma2(h2.y, w0[2*kk + 1], a01);
                a10 = fma2(h2.x, w1[2*kk],     a10);
                a11 = fma2(h2.y, w1[2*kk + 1], a11);
            }
            float2 f00 = unpack2(a00), f01 = unpack2(a01);
            float2 f10 = unpack2(a10), f11 = unpack2(a11);
            float s0 = (f00.x + f01.x) + (f00.y + f01.y);
            float s1 = (f10.x + f11.x) + (f10.y + f11.y);
            s0 += __shfl_xor_sync(0xffffffffu, s0, 16);   // combine k-halves
            s1 += __shfl_xor_sync(0xffffffffu, s1, 16);
            const float h0 = tanh_fast(s0 + eb.x);
            const float h1 = tanh_fast(s1 + eb.y);
            if (half == 0)
                *reinterpret_cast<float2*>(&hbuf[nxt][r][hword]) = make_float2(h0, h1);
        }
        __syncthreads();
    }

    // =========================== output head ===========================
    // final h of row r lives in hbuf[lr[r] & 1][r] (never overwritten after death)
    for (int idx = tid; idx < RR * Oo; idx += NT) {
        const int r = idx / Oo, o = idx % Oo;
        const float* hr = &hbuf[lens_s[r] & 1][r][0];
        float s = b_out[o];
        #pragma unroll 4
        for (int k = 0; k < Hh; k++) {
            const float hv = hr[k + ((k >> 6) << 2)];    // skip the gap
            s = fmaf(fmaxf(hv, 0.0f), Wout_s[o * 129 + k], s);
        }
        logits_s[idx] = s;
    }
    __syncthreads();

    if (tid < RR) {
        float m = -1e30f;
        #pragma unroll
        for (int o = 0; o < Oo; o++) m = fmaxf(m, logits_s[tid * Oo + o]);
        float se = 0.0f;
        #pragma unroll
        for (int o = 0; o < Oo; o++) se += expf(logits_s[tid * Oo + o] - m);
        const float lse = m + logf(se);
        #pragma unroll
        for (int o = 0; o < Oo; o++)
            out[(row0 + tid) * Oo + o] = logits_s[tid * Oo + o] - lse;
    }
}

// ---------------------------------------------------------------------------
extern "C" void kernel_launch(void* const* d_in, const int* in_sizes, int n_in,
                              void* d_out, int out_size) {
    const int*   x     = (const int*)  d_in[0];
    const int*   xlen  = (const int*)  d_in[1];
    const float* emb   = (const float*)d_in[2];
    const float* W_ih  = (const float*)d_in[3];
    const float* W_hh  = (const float*)d_in[4];
    const float* b_ih  = (const float*)d_in[5];
    const float* b_hh  = (const float*)d_in[6];
    const float* W_out = (const float*)d_in[7];
    const float* b_out = (const float*)d_in[8];

    rnn_kernel<<<NCTAS, NT>>>(x, xlen, emb, W_ih, W_hh,
                              b_ih, b_hh, W_out, b_out,
                              (float*)d_out);
}

// round 3
// speedup vs baseline: 1.4777x; 1.0472x over previous
#include <cuda_runtime.h>
#include <cstdint>

// Problem constants (fixed by the reference)
#define Bsz      4096
#define Tmax     512
#define Vv       57
#define Ee       20
#define Hh       128
#define Oo       18

// Partitioning
#define RR       8            // batch rows per CTA
#define NT       128          // 64 column-pairs x 2 k-halves
#define NCTAS    (Bsz / RR)   // 512

// h row layout in smem: words [0..63] = k 0..63, gap [64..67], [68..131] = k 64..127.
// The 4-word gap makes the two half-warp LDS.128 addresses hit disjoint banks.
#define HROW     132

// ---------------------------------------------------------------------------
// packed fp32x2 ops (B300: FFMA2 doubles fp32 FMA throughput; PTX-only)
// ---------------------------------------------------------------------------
__device__ __forceinline__ unsigned long long fma2(unsigned long long a,
                                                   unsigned long long b,
                                                   unsigned long long c) {
    unsigned long long d;
    asm("fma.rn.f32x2 %0, %1, %2, %3;" : "=l"(d) : "l"(a), "l"(b), "l"(c));
    return d;
}
__device__ __forceinline__ unsigned long long add2(unsigned long long a,
                                                   unsigned long long b) {
    unsigned long long d;
    asm("add.rn.f32x2 %0, %1, %2;" : "=l"(d) : "l"(a), "l"(b));
    return d;
}
__device__ __forceinline__ float2 unpack2(unsigned long long v) {
    float2 r;
    asm("mov.b64 {%0, %1}, %2;" : "=f"(r.x), "=f"(r.y) : "l"(v));
    return r;
}
__device__ __forceinline__ float ex2a(float x) {
    float y; asm("ex2.approx.f32 %0, %1;" : "=f"(y) : "f"(x)); return y;
}
__device__ __forceinline__ float rcpa(float x) {
    float y; asm("rcp.approx.f32 %0, %1;" : "=f"(y) : "f"(x)); return y;
}
// tanh: 2 MUFU + few FMA-class ops, ~1e-6 rel err, no overflow (exponent <= 0)
__device__ __forceinline__ float tanh_fast(float x) {
    float ax = fabsf(x);
    float e  = ex2a(ax * -2.885390081777927f);     // exp(-2*ax)
    float t  = (1.0f - e) * rcpa(1.0f + e);
    return copysignf(t, x);
}

// ---------------------------------------------------------------------------
__global__ void __launch_bounds__(NT, 3) rnn_kernel(
    const int*   __restrict__ x,      // [B, T]
    const int*   __restrict__ xlen,   // [B] sorted descending
    const float* __restrict__ emb,    // [V, E]
    const float* __restrict__ W_ih,   // [H, E]
    const float* __restrict__ W_hh,   // [H, H]
    const float* __restrict__ b_ih,   // [H]
    const float* __restrict__ b_hh,   // [H]
    const float* __restrict__ W_out,  // [O, H]
    const float* __restrict__ b_out,  // [O]
    float*       __restrict__ out)    // [B, O]
{
    __shared__ __align__(16) float embW[Vv * Hh];        // 29184 B
    __shared__ __align__(16) float hbuf[2][RR][HROW];    //  8448 B
    __shared__ float Wout_s[Oo * 129];                   //  9288 B
    __shared__ float logits_s[RR * Oo];
    __shared__ int   lens_s[RR];
    __shared__ int   toks[2][RR];

    const int tid  = threadIdx.x;
    const int w    = tid >> 5, l = tid & 31;
    const int jp   = (w << 4) | (l & 15);   // column pair index 0..63
    const int half = l >> 4;                // k half: 0 -> k[0,64), 1 -> k[64,128)
    const int j0   = jp * 2;                // first of the two owned columns
    const int row0 = blockIdx.x * RR;

    // ---- stage emb into hbuf scratch (2112 floats available >= 1140) ----
    float* stage = &hbuf[0][0][0];
    for (int i = tid; i < Vv * Ee; i += NT) stage[i] = emb[i];
    for (int i = tid; i < Oo * Hh; i += NT)
        Wout_s[(i / Hh) * 129 + (i % Hh)] = W_out[i];
    if (tid < RR) {
        lens_s[tid] = xlen[row0 + tid];
        toks[0][tid] = x[(row0 + tid) * Tmax];           // tokens for t=0
    }
    __syncthreads();

    // ---- embW column tid: fused input projection + both biases ----
    {
        float wih[Ee];
        #pragma unroll
        for (int e = 0; e < Ee; e++) wih[e] = W_ih[tid * Ee + e];
        const float bias = b_ih[tid] + b_hh[tid];
        for (int v = 0; v < Vv; v++) {
            float s = bias;
            #pragma unroll
            for (int e = 0; e < Ee; e++) s = fmaf(stage[v * Ee + e], wih[e], s);
            embW[v * Hh + tid] = s;
        }
    }
    __syncthreads();   // stage reads complete before hbuf reuse

    // ---- zero h (buffer 0) ----
    for (int i = tid; i < RR * HROW; i += NT) (&hbuf[0][0][0])[i] = 0.0f;

    // ---- W_hh: two columns (rows of W_hh), this thread's k-half: 128 regs ----
    unsigned long long w0[32], w1[32];
    {
        const ulonglong2* p0 = reinterpret_cast<const ulonglong2*>(W_hh + j0 * Hh + half * 64);
        const ulonglong2* p1 = reinterpret_cast<const ulonglong2*>(W_hh + (j0 + 1) * Hh + half * 64);
        #pragma unroll
        for (int i = 0; i < 16; i++) {
            ulonglong2 a = p0[i]; w0[2*i] = a.x; w0[2*i+1] = a.y;
            ulonglong2 b = p1[i]; w1[2*i] = b.x; w1[2*i+1] = b.y;
        }
    }
    __syncthreads();

    const int hword  = j0 + ((jp >= 32) ? 4 : 0);  // skip the 4-word gap
    const int maxlen = lens_s[0];                  // lengths sorted descending

    // =========================== recurrence ===========================
    for (int t = 0; t < maxlen; t++) {
        const int cur = t & 1, nxt = cur ^ 1;
        // prefetch next step's tokens (latency hidden under this step's math)
        if (tid < RR) {
            const int tt = min(t + 1, Tmax - 1);
            toks[nxt][tid] = x[(row0 + tid) * Tmax + tt];
        }
        // active rows form a prefix (lengths sorted desc); no local-mem array
        int nact = 0;
        #pragma unroll
        for (int r = 0; r < RR; r++) nact += (lens_s[r] > t) ? 1 : 0;

        int r = 0;
        #pragma unroll 1
        for (; r + 2 <= nact; r += 2) {            // two rows interleaved (ILP)
            const int tokA = toks[cur][r];
            const int tokB = toks[cur][r + 1];
            const float2 ebA = *reinterpret_cast<const float2*>(&embW[tokA * Hh + j0]);
            const float2 ebB = *reinterpret_cast<const float2*>(&embW[tokB * Hh + j0]);
            const ulonglong2* hpA =
                reinterpret_cast<const ulonglong2*>(&hbuf[cur][r][half * 68]);
            const ulonglong2* hpB =
                reinterpret_cast<const ulonglong2*>(&hbuf[cur][r + 1][half * 68]);
            unsigned long long a00=0ull, a01=0ull, a10=0ull, a11=0ull;
            unsigned long long b00=0ull, b01=0ull, b10=0ull, b11=0ull;
            #pragma unroll
            for (int kk = 0; kk < 16; kk++) {
                ulonglong2 hA = hpA[kk];           // one LDS.128 feeds 4 FFMA2
                a00 = fma2(hA.x, w0[2*kk],     a00);
                a01 = fma2(hA.y, w0[2*kk + 1], a01);
                a10 = fma2(hA.x, w1[2*kk],     a10);
                a11 = fma2(hA.y, w1[2*kk + 1], a11);
                ulonglong2 hB = hpB[kk];
                b00 = fma2(hB.x, w0[2*kk],     b00);
                b01 = fma2(hB.y, w0[2*kk + 1], b01);
                b10 = fma2(hB.x, w1[2*kk],     b10);
                b11 = fma2(hB.y, w1[2*kk + 1], b11);
            }
            float2 fA0 = unpack2(add2(a00, a01));
            float2 fA1 = unpack2(add2(a10, a11));
            float2 fB0 = unpack2(add2(b00, b01));
            float2 fB1 = unpack2(add2(b10, b11));
            float sA0 = fA0.x + fA0.y, sA1 = fA1.x + fA1.y;
            float sB0 = fB0.x + fB0.y, sB1 = fB1.x + fB1.y;
            sA0 += __shfl_xor_sync(0xffffffffu, sA0, 16);   // combine k-halves
            sA1 += __shfl_xor_sync(0xffffffffu, sA1, 16);
            sB0 += __shfl_xor_sync(0xffffffffu, sB0, 16);
            sB1 += __shfl_xor_sync(0xffffffffu, sB1, 16);
            const float hA0 = tanh_fast(sA0 + ebA.x);
            const float hA1 = tanh_fast(sA1 + ebA.y);
            const float hB0 = tanh_fast(sB0 + ebB.x);
            const float hB1 = tanh_fast(sB1 + ebB.y);
            if (half == 0) {
                *reinterpret_cast<float2*>(&hbuf[nxt][r][hword])     = make_float2(hA0, hA1);
                *reinterpret_cast<float2*>(&hbuf[nxt][r + 1][hword]) = make_float2(hB0, hB1);
            }
        }
        if (r < nact) {                            // odd remainder row
            const int tok = toks[cur][r];
            const float2 eb = *reinterpret_cast<const float2*>(&embW[tok * Hh + j0]);
            const ulonglong2* hp =
                reinterpret_cast<const ulonglong2*>(&hbuf[cur][r][half * 68]);
            unsigned long long a00=0ull, a01=0ull, a10=0ull, a11=0ull;
            #pragma unroll
            for (int kk = 0; kk < 16; kk++) {
                ulonglong2 h2 = hp[kk];
                a00 = fma2(h2.x, w0[2*kk],     a00);
                a01 = fma2(h2.y, w0[2*kk + 1], a01);
                a10 = fma2(h2.x, w1[2*kk],     a10);
                a11 = fma2(h2.y, w1[2*kk + 1], a11);
            }
            float2 f0 = unpack2(add2(a00, a01));
            float2 f1 = unpack2(add2(a10, a11));
            float s0 = f0.x + f0.y, s1 = f1.x + f1.y;
            s0 += __shfl_xor_sync(0xffffffffu, s0, 16);
            s1 += __shfl_xor_sync(0xffffffffu, s1, 16);
            const float h0 = tanh_fast(s0 + eb.x);
            const float h1 = tanh_fast(s1 + eb.y);
            if (half == 0)
                *reinterpret_cast<float2*>(&hbuf[nxt][r][hword]) = make_float2(h0, h1);
        }
        __syncthreads();
    }

    // =========================== output head ===========================
    // final h of row r lives in hbuf[lens_s[r] & 1][r] (untouched after death)
    for (int idx = tid; idx < RR * Oo; idx += NT) {
        const int r = idx / Oo, o = idx % Oo;
        const float* hr = &hbuf[lens_s[r] & 1][r][0];
        float s = b_out[o];
        #pragma unroll 4
        for (int k = 0; k < Hh; k++) {
            const float hv = hr[k + ((k >> 6) << 2)];    // skip the gap
            s = fmaf(fmaxf(hv, 0.0f), Wout_s[o * 129 + k], s);
        }
        logits_s[idx] = s;
    }
    __syncthreads();

    if (tid < RR) {
        float m = -1e30f;
        #pragma unroll
        for (int o = 0; o < Oo; o++) m = fmaxf(m, logits_s[tid * Oo + o]);
        float se = 0.0f;
        #pragma unroll
        for (int o = 0; o < Oo; o++) se += expf(logits_s[tid * Oo + o] - m);
        const float lse = m + logf(se);
        #pragma unroll
        for (int o = 0; o < Oo; o++)
            out[(row0 + tid) * Oo + o] = logits_s[tid * Oo + o] - lse;
    }
}

// ---------------------------------------------------------------------------
extern "C" void kernel_launch(void* const* d_in, const int* in_sizes, int n_in,
                              void* d_out, int out_size) {
    const int*   x     = (const int*)  d_in[0];
    const int*   xlen  = (const int*)  d_in[1];
    const float* emb   = (const float*)d_in[2];
    const float* W_ih  = (const float*)d_in[3];
    const float* W_hh  = (const float*)d_in[4];
    const float* b_ih  = (const float*)d_in[5];
    const float* b_hh  = (const float*)d_in[6];
    const float* W_out = (const float*)d_in[7];
    const float* b_out = (const float*)d_in[8];

    rnn_kernel<<<NCTAS, NT>>>(x, xlen, emb, W_ih, W_hh,
                              b_ih, b_hh, W_out, b_out,
                              (float*)d_out);
}

// round 4
// speedup vs baseline: 2.0282x; 1.3725x over previous
#include <cuda_runtime.h>
#include <cstdint>

// Problem constants (fixed by the reference)
#define Bsz      4096
#define Tmax     512
#define Vv       57
#define Ee       20
#define Hh       128
#define Oo       18

// Partitioning: 2 CTAs/SM, 16 warps/SM
#define RR       8            // batch rows per CTA
#define NT       256          // 64 col-pairs x 4 k-quarters
#define NCTAS    (Bsz / RR)   // 512

// h row layout: k lives at word (k>>5)*36 + (k&31); row stride 148 words.
// Quarter bases {0,36,72,108} -> banks {0,4,8,12}: conflict-free LDS.128.
#define HROW     148

typedef unsigned long long ull;

__device__ float g_embW[Vv * Hh];   // embW[v][j] = emb[v]@W_ih[j] + b_ih[j] + b_hh[j]

// ---------------------------------------------------------------------------
__device__ __forceinline__ ull fma2(ull a, ull b, ull c) {
    ull d;
    asm("fma.rn.f32x2 %0, %1, %2, %3;" : "=l"(d) : "l"(a), "l"(b), "l"(c));
    return d;
}
__device__ __forceinline__ float hadd2(ull v) {
    float lo, hi;
    asm("mov.b64 {%0, %1}, %2;" : "=f"(lo), "=f"(hi) : "l"(v));
    return lo + hi;
}
__device__ __forceinline__ float ex2a(float x) {
    float y; asm("ex2.approx.f32 %0, %1;" : "=f"(y) : "f"(x)); return y;
}
__device__ __forceinline__ float rcpa(float x) {
    float y; asm("rcp.approx.f32 %0, %1;" : "=f"(y) : "f"(x)); return y;
}
__device__ __forceinline__ float tanh_fast(float x) {
    float ax = fabsf(x);
    float e  = ex2a(ax * -2.885390081777927f);     // exp(-2*ax)
    float t  = (1.0f - e) * rcpa(1.0f + e);
    return copysignf(t, x);
}

// ---------------------------------------------------------------------------
// Pre-kernel: fused input projection table (57 x 128, lives in L2 afterwards)
// ---------------------------------------------------------------------------
__global__ void embw_kernel(const float* __restrict__ emb,
                            const float* __restrict__ W_ih,
                            const float* __restrict__ b_ih,
                            const float* __restrict__ b_hh) {
    const int v = blockIdx.x, j = threadIdx.x;
    float s = b_ih[j] + b_hh[j];
    #pragma unroll
    for (int e = 0; e < Ee; e++) s = fmaf(emb[v * Ee + e], W_ih[j * Ee + e], s);
    g_embW[v * Hh + j] = s;
}

// ---------------------------------------------------------------------------
// 4-row group: every thread accumulates its 2 cols x 32 k for rows br..br+3,
// reduce-scatter over the 4 k-quarters (3 shfl per col), quarter q finalizes
// row br+q (tanh + store + predicated final-capture).
// ---------------------------------------------------------------------------
#define GROUP(br, EB, LEN)                                                     \
{                                                                              \
    const ulonglong2* h0 = (const ulonglong2*)(hc + ((br)+0)*HROW + q*36);     \
    const ulonglong2* h1 = (const ulonglong2*)(hc + ((br)+1)*HROW + q*36);     \
    const ulonglong2* h2 = (const ulonglong2*)(hc + ((br)+2)*HROW + q*36);     \
    const ulonglong2* h3 = (const ulonglong2*)(hc + ((br)+3)*HROW + q*36);     \
    ull a00=0,a01=0,a10=0,a11=0,a20=0,a21=0,a30=0,a31=0;                       \
    _Pragma("unroll")                                                          \
    for (int i = 0; i < 8; i++) {                                              \
        ulonglong2 c0 = h0[i], c1 = h1[i], c2 = h2[i], c3 = h3[i];             \
        a00 = fma2(c0.x, w0[2*i], a00); a00 = fma2(c0.y, w0[2*i+1], a00);      \
        a01 = fma2(c0.x, w1[2*i], a01); a01 = fma2(c0.y, w1[2*i+1], a01);      \
        a10 = fma2(c1.x, w0[2*i], a10); a10 = fma2(c1.y, w0[2*i+1], a10);      \
        a11 = fma2(c1.x, w1[2*i], a11); a11 = fma2(c1.y, w1[2*i+1], a11);      \
        a20 = fma2(c2.x, w0[2*i], a20); a20 = fma2(c2.y, w0[2*i+1], a20);      \
        a21 = fma2(c2.x, w1[2*i], a21); a21 = fma2(c2.y, w1[2*i+1], a21);      \
        a30 = fma2(c3.x, w0[2*i], a30); a30 = fma2(c3.y, w0[2*i+1], a30);      \
        a31 = fma2(c3.x, w1[2*i], a31); a31 = fma2(c3.y, w1[2*i+1], a31);      \
    }                                                                          \
    float v00 = hadd2(a00), v10 = hadd2(a10), v20 = hadd2(a20), v30 = hadd2(a30);\
    float v01 = hadd2(a01), v11 = hadd2(a11), v21 = hadd2(a21), v31 = hadd2(a31);\
    /* reduce-scatter over quarters: lane q ends with full sum of row br+q */  \
    float ua0 = (b1 ? v20 : v00) + __shfl_xor_sync(~0u, b1 ? v00 : v20, 16);   \
    float ub0 = (b1 ? v30 : v10) + __shfl_xor_sync(~0u, b1 ? v10 : v30, 16);   \
    float s0  = (b0 ? ub0 : ua0) + __shfl_xor_sync(~0u, b0 ? ua0 : ub0, 8);    \
    float ua1 = (b1 ? v21 : v01) + __shfl_xor_sync(~0u, b1 ? v01 : v21, 16);   \
    float ub1 = (b1 ? v31 : v11) + __shfl_xor_sync(~0u, b1 ? v11 : v31, 16);   \
    float s1  = (b0 ? ub1 : ua1) + __shfl_xor_sync(~0u, b0 ? ua1 : ub1, 8);    \
    const float hx = tanh_fast(s0 + (EB).x);                                   \
    const float hy = tanh_fast(s1 + (EB).y);                                   \
    *(float2*)(hn  + ((br)+q)*HROW + cw) = make_float2(hx, hy);                \
    if (t == (LEN) - 1)                                                        \
        *(float2*)(hfin + ((br)+q)*HROW + cw) = make_float2(hx, hy);           \
}

// ---------------------------------------------------------------------------
__global__ void __launch_bounds__(NT, 2) rnn_kernel(
    const int*   __restrict__ x,      // [B, T]
    const int*   __restrict__ xlen,   // [B] sorted descending
    const float* __restrict__ W_hh,   // [H, H]
    const float* __restrict__ W_out,  // [O, H]
    const float* __restrict__ b_out,  // [O]
    float*       __restrict__ out)    // [B, O]
{
    __shared__ __align__(16) float hbuf[2][RR * HROW];   // 9472 B
    __shared__ __align__(16) float hfin[RR * HROW];      // 4736 B
    __shared__ float Wout_s[Oo * 129];                   // 9288 B
    __shared__ float logits_s[RR * Oo];
    __shared__ int   lens_s[RR];
    __shared__ int   toks[4][RR];                        // token ring (t mod 4)

    const int tid = threadIdx.x;
    const int l = tid & 31, w = tid >> 5;
    const int q  = l >> 3;              // k-quarter 0..3 (k in [q*32, q*32+32))
    const int p  = l & 7;               // col-pair within warp
    const int j0 = (w * 8 + p) * 2;     // first owned column
    const int cw = ((j0 >> 5) * 36) + (j0 & 31);   // gapped word of col j0
    const bool b1 = (q & 2) != 0, b0 = (q & 1) != 0;
    const int row0 = blockIdx.x * RR;

    // ---- staging ----
    for (int i = tid; i < Oo * Hh; i += NT)
        Wout_s[(i / Hh) * 129 + (i % Hh)] = W_out[i];
    const int* xp = x + (row0 + (tid & 7)) * Tmax;       // valid for tid < 8
    if (tid < RR) {
        lens_s[tid] = xlen[row0 + tid];
        toks[0][tid] = xp[0];
        toks[1][tid] = xp[1];
    }
    for (int i = tid; i < RR * HROW; i += NT) hbuf[0][i] = 0.0f;
    __syncthreads();

    // ---- W_hh: 2 cols x 32 k -> 64 floats in registers ----
    ull w0[16], w1[16];
    {
        const ulonglong2* p0 = (const ulonglong2*)(W_hh + j0 * Hh + q * 32);
        const ulonglong2* p1 = (const ulonglong2*)(W_hh + (j0 + 1) * Hh + q * 32);
        #pragma unroll
        for (int i = 0; i < 8; i++) {
            ulonglong2 a = p0[i]; w0[2*i] = a.x; w0[2*i+1] = a.y;
            ulonglong2 b = p1[i]; w1[2*i] = b.x; w1[2*i+1] = b.y;
        }
    }

    const int maxlen = lens_s[0];           // lengths sorted descending
    const int len0 = lens_s[q];             // this thread finalizes rows q, 4+q
    const int len1 = lens_s[4 + q];

    // eb prefetch for t = 0
    float2 ebn0, ebn1;
    {
        const int tk0 = toks[0][q], tk1 = toks[0][4 + q];
        ebn0 = *(const float2*)&g_embW[tk0 * Hh + j0];
        ebn1 = *(const float2*)&g_embW[tk1 * Hh + j0];
    }

    // =========================== recurrence ===========================
    for (int t = 0; t < maxlen; t++) {
        const int cur = t & 1;
        const float* hc = hbuf[cur];
        float*       hn = hbuf[cur ^ 1];

        // token prefetch two steps ahead (ring slot (t+2)&3)
        if (tid < RR) {
            const int tt = min(t + 2, Tmax - 1);
            toks[(t + 2) & 3][tid] = xp[tt];
        }
        // consume this step's eb, prefetch next step's (tokens written at t-1)
        const float2 eb0 = ebn0, eb1 = ebn1;
        {
            const int ni = (t + 1) & 3;
            const int tk0 = toks[ni][q], tk1 = toks[ni][4 + q];
            ebn0 = *(const float2*)&g_embW[tk0 * Hh + j0];
            ebn1 = *(const float2*)&g_embW[tk1 * Hh + j0];
        }

        GROUP(0, eb0, len0)
        GROUP(4, eb1, len1)

        __syncthreads();
    }

    // =========================== output head ===========================
    for (int idx = tid; idx < RR * Oo; idx += NT) {
        const int r = idx / Oo, o = idx % Oo;
        const float* hr = hfin + r * HROW;
        float s = b_out[o];
        #pragma unroll 4
        for (int k = 0; k < Hh; k++) {
            const float hv = hr[(k >> 5) * 36 + (k & 31)];
            s = fmaf(fmaxf(hv, 0.0f), Wout_s[o * 129 + k], s);
        }
        logits_s[idx] = s;
    }
    __syncthreads();

    if (tid < RR) {
        float m = -1e30f;
        #pragma unroll
        for (int o = 0; o < Oo; o++) m = fmaxf(m, logits_s[tid * Oo + o]);
        float se = 0.0f;
        #pragma unroll
        for (int o = 0; o < Oo; o++) se += expf(logits_s[tid * Oo + o] - m);
        const float lse = m + logf(se);
        #pragma unroll
        for (int o = 0; o < Oo; o++)
            out[(row0 + tid) * Oo + o] = logits_s[tid * Oo + o] - lse;
    }
}

// ---------------------------------------------------------------------------
extern "C" void kernel_launch(void* const* d_in, const int* in_sizes, int n_in,
                              void* d_out, int out_size) {
    const int*   x     = (const int*)  d_in[0];
    const int*   xlen  = (const int*)  d_in[1];
    const float* emb   = (const float*)d_in[2];
    const float* W_ih  = (const float*)d_in[3];
    const float* W_hh  = (const float*)d_in[4];
    const float* b_ih  = (const float*)d_in[5];
    const float* b_hh  = (const float*)d_in[6];
    const float* W_out = (const float*)d_in[7];
    const float* b_out = (const float*)d_in[8];

    embw_kernel<<<Vv, Hh>>>(emb, W_ih, b_ih, b_hh);
    rnn_kernel<<<NCTAS, NT>>>(x, xlen, W_hh, W_out, b_out, (float*)d_out);
}